// round 16
// baseline (speedup 1.0000x reference)
#include <cuda_runtime.h>
#include <cuda_fp16.h>
#include <cstddef>

// Problem constants
#define BB 2
#define SS 2048
#define HH 768
#define NHEAD 12
#define HD 64
#define MM (BB*SS)          // 4096
#define SCALE 0.125f        // HD^-0.5
#define L2E 1.4426950408889634f
#define SCALE2 (SCALE*L2E)  // fold into logit: s' = s*log2(e)
#define HC (0.5f*L2E)

// ---------------------------------------------------------------------------
// Device scratch
// ---------------------------------------------------------------------------
__device__ __half g_hh[(size_t)MM*HH];                 // hidden in fp16
__device__ __half g_q [(size_t)3*BB*NHEAD*SS*HD];
__device__ __half g_k [(size_t)3*BB*NHEAD*SS*HD];
__device__ __half g_vt[(size_t)3*BB*NHEAD*SS*HD];      // V transposed: [n][bh][d][s]
__device__ __half g_ctx[(size_t)3*MM*HH];
__device__ __half g_wt[(size_t)12*HH*HH];              // transposed fp16 weights
__device__ float  g_stm[(size_t)2*24*SS];              // row max (log2 domain) n=0,1
__device__ float  g_sti[(size_t)2*24*SS];              // row 1/sum n=0,1
__device__ __half g_sl[(size_t)2*24*SS*SS];            // masked log2 logits s0',s1' (fp16)
// flash_b split-j partials (2 halves)
__device__ float  g_po[(size_t)2*24*SS*HD];            // partial o (unnormalized)
__device__ float  g_pm[(size_t)2*24*SS];               // partial row max (log2)
__device__ float  g_pl[(size_t)2*24*SS];               // partial row sum

// ---------------------------------------------------------------------------
// fp16 mma helpers (m16n8k16, fp32 accumulate)
// ---------------------------------------------------------------------------
__device__ __forceinline__ void mma16(float c[4], const unsigned a[4], const unsigned b[2]){
    asm volatile("mma.sync.aligned.m16n8k16.row.col.f32.f16.f16.f32 "
        "{%0,%1,%2,%3},{%4,%5,%6,%7},{%8,%9},{%0,%1,%2,%3};"
        : "+f"(c[0]),"+f"(c[1]),"+f"(c[2]),"+f"(c[3])
        : "r"(a[0]),"r"(a[1]),"r"(a[2]),"r"(a[3]),"r"(b[0]),"r"(b[1]));
}
__device__ __forceinline__ void ldsm4(unsigned r[4], unsigned saddr){
    asm volatile("ldmatrix.sync.aligned.m8n8.x4.shared.b16 {%0,%1,%2,%3}, [%4];"
        : "=r"(r[0]),"=r"(r[1]),"=r"(r[2]),"=r"(r[3]) : "r"(saddr));
}
__device__ __forceinline__ unsigned packh2(float a, float b){
    __half2 h = __floats2half2_rn(a, b);
    return *reinterpret_cast<unsigned*>(&h);
}
// raw MUFU.EX2 fp32
__device__ __forceinline__ float ex2(float x){
    float r; asm("ex2.approx.f32 %0, %1;" : "=f"(r) : "f"(x)); return r;
}
// packed half2 exp2 on MUFU (2 values / instruction)
__device__ __forceinline__ unsigned h2ex2(unsigned x){
    unsigned r; asm("ex2.approx.f16x2 %0, %1;" : "=r"(r) : "r"(x)); return r;
}

// cp.async 16B (8 halfs)
__device__ __forceinline__ void cp16h(unsigned* s, const __half* g){
    unsigned sa = (unsigned)__cvta_generic_to_shared(s);
    asm volatile("cp.async.cg.shared.global [%0], [%1], 16;" :: "r"(sa), "l"(g));
}
#define CP_COMMIT()   asm volatile("cp.async.commit_group;")
#define CP_WAIT(N)    asm volatile("cp.async.wait_group %0;" :: "n"(N))

// Async load of a [ROWS x 64] k-major half tile (row stride ld halfs) into smem.
template<int ROWS>
__device__ __forceinline__ void load_tile_async_h(unsigned* s, const __half* __restrict__ g,
                                                  size_t ld, int k0, int tid){
#pragma unroll
    for(int i=0;i<ROWS*8/256;i++){
        int idx = i*256 + tid;
        int row = idx>>3, c = idx&7;
        cp16h(s + (row<<5) + ((c ^ (row&7))<<2), g + (size_t)row*ld + k0 + 8*c);
    }
}

// One BK=64 block-step via ldmatrix. Warp tile = MI m16 x NI n8 (NI even).
template<int MI,int NI>
__device__ __forceinline__ void mma_block_h(const unsigned* sA, const unsigned* sB,
        int wm_base, int wn_base, int gid, int tig, float acc[MI][NI][4]){
    (void)gid; (void)tig;
    const int lane = threadIdx.x & 31;
    const unsigned baseA = (unsigned)__cvta_generic_to_shared(sA);
    const unsigned baseB = (unsigned)__cvta_generic_to_shared(sB);
    const int rA0 = wm_base + (lane & 15);
    const int gA  = lane >> 4;
    const int q   = lane >> 3;
    const int rB0 = wn_base + (lane & 7) + ((q >> 1) << 3);
    const int gB  = q & 1;
#pragma unroll
    for(int ks=0;ks<4;ks++){
        unsigned af[MI][4], bf[NI][2];
#pragma unroll
        for(int mi=0;mi<MI;mi++){
            const int row = rA0 + mi*16;
            const int grp = 2*ks + gA;
            ldsm4(af[mi], baseA + (row<<7) + ((grp ^ (row&7))<<4));
        }
#pragma unroll
        for(int np=0;np<NI/2;np++){
            const int row = rB0 + np*16;
            const int grp = 2*ks + gB;
            unsigned t[4];
            ldsm4(t, baseB + (row<<7) + ((grp ^ (row&7))<<4));
            bf[np*2  ][0]=t[0]; bf[np*2  ][1]=t[1];
            bf[np*2+1][0]=t[2]; bf[np*2+1][1]=t[3];
        }
#pragma unroll
        for(int mi=0;mi<MI;mi++)
#pragma unroll
            for(int ni=0;ni<NI;ni++)
                mma16(acc[mi][ni], af[mi], bf[ni]);
    }
}

// ---------------------------------------------------------------------------
// K0: convert hidden fp32 -> fp16.
// ---------------------------------------------------------------------------
__global__ void __launch_bounds__(256) conv_hidden(const float* __restrict__ X)
{
    size_t i = ((size_t)blockIdx.x*256 + threadIdx.x)*8;
    float4 a = *(const float4*)(X + i);
    float4 b = *(const float4*)(X + i + 4);
    __align__(16) __half2 h[4];
    h[0] = __floats2half2_rn(a.x, a.y);
    h[1] = __floats2half2_rn(a.z, a.w);
    h[2] = __floats2half2_rn(b.x, b.y);
    h[3] = __floats2half2_rn(b.z, b.w);
    *(uint4*)(g_hh + i) = *(uint4*)h;
}

// ---------------------------------------------------------------------------
// K0a: transpose + fp16-convert the 12 weight matrices [h][e] -> g_wt[mat][e][h]
// ---------------------------------------------------------------------------
__global__ void __launch_bounds__(256) transpose_w(
    const float* __restrict__ Wq, const float* __restrict__ Wk,
    const float* __restrict__ Wv, const float* __restrict__ Wo)
{
    __shared__ __half t[32][33];
    const int mat = blockIdx.z;
    const float* src = (mat<3?Wq:mat<6?Wk:mat<9?Wv:Wo) + (size_t)(mat%3)*HH*HH;
    __half* dst = g_wt + (size_t)mat*HH*HH;
    const int x0 = blockIdx.x*32, y0 = blockIdx.y*32;
    const int tx = threadIdx.x & 31, ty = threadIdx.x >> 5;
#pragma unroll
    for(int r=0;r<4;r++) t[ty+8*r][tx] = __float2half_rn(src[(size_t)(y0+ty+8*r)*HH + x0 + tx]);
    __syncthreads();
#pragma unroll
    for(int r=0;r<4;r++) dst[(size_t)(x0+ty+8*r)*HH + y0 + tx] = t[tx][ty+8*r];
}

// ---------------------------------------------------------------------------
// Generic double-buffered fp16 GEMM body (proj/outproj): MI=NI=4, BK=64.
// ---------------------------------------------------------------------------
template<int KTOT,int AR,int BR>
__device__ __forceinline__ void gemm_body_h(
    unsigned* sA, unsigned* sB,
    const __half* __restrict__ A, size_t lda,
    const __half* __restrict__ B, size_t ldb,
    int tid, int wm_base, int wn_base, int gid, int tig,
    float acc[4][4][4])
{
    load_tile_async_h<AR>(sA, A, lda, 0, tid);
    load_tile_async_h<BR>(sB, B, ldb, 0, tid);
    CP_COMMIT();
    const int nk = KTOT/64;
#pragma unroll 1
    for(int kt=0; kt<nk; kt++){
        const int cur = kt & 1, nxt = cur ^ 1;
        if(kt+1 < nk){
            load_tile_async_h<AR>(sA + nxt*AR*32, A, lda, (kt+1)*64, tid);
            load_tile_async_h<BR>(sB + nxt*BR*32, B, ldb, (kt+1)*64, tid);
        }
        CP_COMMIT();
        CP_WAIT(1);
        __syncthreads();
        mma_block_h<4,4>(sA + cur*AR*32, sB + cur*BR*32, wm_base, wn_base, gid, tig, acc);
        __syncthreads();
    }
}

// ---------------------------------------------------------------------------
// K1: QKV projection.  Block 128x128. grid (6, 32, 9). fp16 in/out.
// t==2 (V): stage in smem and write DIRECTLY TRANSPOSED into g_vt.
// ---------------------------------------------------------------------------
__global__ void __launch_bounds__(256,2) proj_tc(
    const float* __restrict__ bq, const float* __restrict__ bk, const float* __restrict__ bv)
{
    extern __shared__ unsigned smu[];
    unsigned* sA = smu;
    unsigned* sB = smu + 2*128*32;
    const int z = blockIdx.z, n = z%3, t = z/3;
    const __half* Wt  = g_wt + (size_t)(t*3+n)*HH*HH;
    const float* bias = (t==0?bq:(t==1?bk:bv)) + (size_t)n*HH;

    const int m0 = blockIdx.y*128, e0 = blockIdx.x*128;
    const int tid = threadIdx.x, wid = tid>>5, lane = tid&31;
    const int gid = lane>>2, tig = lane&3;
    const int wm = wid & 1, wn = wid >> 1;

    float acc[4][4][4] = {};
    gemm_body_h<HH,128,128>(sA, sB, g_hh + (size_t)m0*HH, HH, Wt + (size_t)e0*HH, HH,
                            tid, wm*64, wn*32, gid, tig, acc);

    if(t < 2){
        __half* O = (t==0 ? g_q : g_k) + (size_t)n*BB*NHEAD*SS*HD;
#pragma unroll
        for(int mi=0;mi<4;mi++)
#pragma unroll
        for(int ni=0;ni<4;ni++){
            const int e = e0 + wn*32 + ni*8 + 2*tig;
            const float2 b2 = *(const float2*)(bias + e);
            const int head = e>>6, d = e&63;
#pragma unroll
            for(int h2=0;h2<2;h2++){
                int m = m0 + wm*64 + mi*16 + gid + h2*8;
                int b = m>>11, s = m & (SS-1);
                __half2 o = __floats2half2_rn(acc[mi][ni][h2*2+0] + b2.x,
                                              acc[mi][ni][h2*2+1] + b2.y);
                *(__half2*)(O + (((size_t)b*NHEAD + head)*SS + s)*HD + d) = o;
            }
        }
    } else {
        __half* st = (__half*)smu;   // 128*136 halfs
#pragma unroll
        for(int mi=0;mi<4;mi++)
#pragma unroll
        for(int ni=0;ni<4;ni++){
            const int el = wn*32 + ni*8 + 2*tig;
            const float2 b2 = *(const float2*)(bias + e0 + el);
#pragma unroll
            for(int h2=0;h2<2;h2++){
                const int ml = wm*64 + mi*16 + gid + h2*8;
                st[(el  )*136 + ml] = __float2half_rn(acc[mi][ni][h2*2+0] + b2.x);
                st[(el+1)*136 + ml] = __float2half_rn(acc[mi][ni][h2*2+1] + b2.y);
            }
        }
        __syncthreads();
        const int b = m0 >> 11, sb = m0 & (SS-1);
#pragma unroll
        for(int r=0;r<8;r++){
            const int idx = r*256 + tid;
            const int el = idx >> 4, c8 = (idx & 15)*8;
            const int head = 2*blockIdx.x + (el>>6), d = el & 63;
            uint4 v = *(uint4*)&st[el*136 + c8];
            *(uint4*)(g_vt + ((size_t)(n*24 + b*NHEAD + head))*SS*HD
                           + (size_t)d*SS + sb + c8) = v;
        }
    }
}

// ---------------------------------------------------------------------------
// K2: flash_a — fused QK^T + online softmax + PV for n = 0,1. (3-stage)
// Also stores masked log2 logits s' (fp16) for flash_b.
// grid (16 i-stripes, 24 bh, 2 n), 256 threads.
// ---------------------------------------------------------------------------
__global__ void __launch_bounds__(256,2) flash_a(const int* __restrict__ mask)
{
    extern __shared__ unsigned smu[];
    float*    maskadd = (float*)smu;            // 2048 floats (pre-scaled by L2E)
    unsigned* qs = smu + 2048;                  // 128x32
    unsigned* kt = qs + 4096;                   // 3 x 64x32
    unsigned* vt = kt + 3*2048;                 // 3 x 64x32

    const int ib = blockIdx.x, bh = blockIdx.y, n = blockIdx.z;
    const int b = bh/NHEAD, h = bh%NHEAD;
    const int i0 = ib*128;
    const __half* qg = g_q  + ((size_t)n*24 + bh)*SS*HD + (size_t)i0*HD;
    const __half* kg = g_k  + ((size_t)n*24 + bh)*SS*HD;
    const __half* vg = g_vt + ((size_t)n*24 + bh)*SS*HD;

    const int tid = threadIdx.x, w = tid>>5, lane = tid&31;
    const int g = lane>>2, t = lane&3, qq = lane>>3;
    const int rA0 = 16*w + (lane&15), gA = lane>>4;
    const int rB0 = (lane&7) + ((qq>>1)<<3), gB = qq&1;

    for(int j = tid; j < SS; j += 256)
        maskadd[j] = mask[b*SS + j] ? 0.f : -43281.f;   // -30000 * log2(e)

    load_tile_async_h<128>(qs, qg, HD, 0, tid);
    load_tile_async_h<64>(kt, kg, HD, 0, tid);
    load_tile_async_h<64>(vt, vg, SS, 0, tid);
    CP_COMMIT();
    CP_WAIT(0);
    __syncthreads();

    unsigned qf[4][4];
    const unsigned qBase = (unsigned)__cvta_generic_to_shared(qs);
#pragma unroll
    for(int kg2=0;kg2<4;kg2++){
        const int grp = 2*kg2 + gA;
        ldsm4(qf[kg2], qBase + (rA0<<7) + ((grp ^ (rA0&7))<<4));
    }
    load_tile_async_h<64>(kt + 2048, kg + (size_t)64*HD, HD, 0, tid);
    load_tile_async_h<64>(vt + 2048, vg, SS, 64, tid);
    CP_COMMIT();
    load_tile_async_h<64>(kt + 4096, kg + (size_t)128*HD, HD, 0, tid);
    load_tile_async_h<64>(vt + 4096, vg, SS, 128, tid);
    CP_COMMIT();

    float o[8][4] = {};
    float m_lo=-1e30f, m_hi=-1e30f, l_lo=0.f, l_hi=0.f;
    const unsigned kBase = (unsigned)__cvta_generic_to_shared(kt);
    const unsigned vBase = (unsigned)__cvta_generic_to_shared(vt);
    const unsigned ones2[2] = {0x3C003C00u, 0x3C003C00u};
    const int r_lo = i0 + 16*w + g, r_hi = r_lo + 8;
    __half* sp_lo = g_sl + (((size_t)n*24 + bh)*SS + r_lo)*SS;
    __half* sp_hi = g_sl + (((size_t)n*24 + bh)*SS + r_hi)*SS;

    int sl = 0;
#pragma unroll 1
    for(int jt=0; jt<32; jt++){
        CP_WAIT(2);
        __syncthreads();
        const unsigned kB = kBase + sl*8192;
        const unsigned vB = vBase + sl*8192;

        // QK^T
        float s[8][4] = {};
#pragma unroll
        for(int ks=0;ks<4;ks++){
            unsigned bf[8][2];
#pragma unroll
            for(int np=0;np<4;np++){
                const int row = rB0 + np*16;
                unsigned tt[4];
                ldsm4(tt, kB + (row<<7) + (((2*ks+gB) ^ (row&7))<<4));
                bf[2*np][0]=tt[0]; bf[2*np][1]=tt[1];
                bf[2*np+1][0]=tt[2]; bf[2*np+1][1]=tt[3];
            }
#pragma unroll
            for(int ni=0;ni<8;ni++) mma16(s[ni], qf[ks], bf[ni]);
        }
        // scale+mask (log2 domain) + store s' + row max (fp32)
        const int jb = jt*64;
        float mx_lo=-1e30f, mx_hi=-1e30f;
#pragma unroll
        for(int ni=0;ni<8;ni++){
            float2 mk = *(const float2*)&maskadd[jb + 8*ni + 2*t];
            s[ni][0] = fmaf(s[ni][0], SCALE2, mk.x);
            s[ni][1] = fmaf(s[ni][1], SCALE2, mk.y);
            s[ni][2] = fmaf(s[ni][2], SCALE2, mk.x);
            s[ni][3] = fmaf(s[ni][3], SCALE2, mk.y);
            *(unsigned*)(sp_lo + jb + 8*ni + 2*t) = packh2(s[ni][0], s[ni][1]);
            *(unsigned*)(sp_hi + jb + 8*ni + 2*t) = packh2(s[ni][2], s[ni][3]);
            mx_lo = fmaxf(mx_lo, fmaxf(s[ni][0], s[ni][1]));
            mx_hi = fmaxf(mx_hi, fmaxf(s[ni][2], s[ni][3]));
        }
        mx_lo = fmaxf(mx_lo, __shfl_xor_sync(0xffffffffu, mx_lo, 1));
        mx_lo = fmaxf(mx_lo, __shfl_xor_sync(0xffffffffu, mx_lo, 2));
        mx_hi = fmaxf(mx_hi, __shfl_xor_sync(0xffffffffu, mx_hi, 1));
        mx_hi = fmaxf(mx_hi, __shfl_xor_sync(0xffffffffu, mx_hi, 2));
        const float mn_lo = fmaxf(m_lo, mx_lo), mn_hi = fmaxf(m_hi, mx_hi);
        const float f_lo = ex2(m_lo - mn_lo), f_hi = ex2(m_hi - mn_hi);
        m_lo = mn_lo; m_hi = mn_hi;

        // exp via f16x2 MUFU; output IS the mma A fragment
        unsigned pf[4][4];
#pragma unroll
        for(int ni=0;ni<8;ni++){
            pf[ni>>1][(ni&1)*2+0] = h2ex2(packh2(s[ni][0]-m_lo, s[ni][1]-m_lo));
            pf[ni>>1][(ni&1)*2+1] = h2ex2(packh2(s[ni][2]-m_hi, s[ni][3]-m_hi));
        }
        // exact row sums of the quantized p via ones-mma
        float ls[4] = {};
#pragma unroll
        for(int kg2=0;kg2<4;kg2++) mma16(ls, pf[kg2], ones2);
        l_lo = l_lo*f_lo + ls[0];
        l_hi = l_hi*f_hi + ls[2];
        if(__any_sync(0xffffffffu, (f_lo < 1.f) | (f_hi < 1.f))){
#pragma unroll
            for(int ni=0;ni<8;ni++){
                o[ni][0]*=f_lo; o[ni][1]*=f_lo; o[ni][2]*=f_hi; o[ni][3]*=f_hi;
            }
        }
        // PV
#pragma unroll
        for(int kg2=0;kg2<4;kg2++){
            unsigned bf[8][2];
#pragma unroll
            for(int np=0;np<4;np++){
                const int row = rB0 + np*16;
                unsigned tt[4];
                ldsm4(tt, vB + (row<<7) + (((2*kg2+gB) ^ (row&7))<<4));
                bf[2*np][0]=tt[0]; bf[2*np][1]=tt[1];
                bf[2*np+1][0]=tt[2]; bf[2*np+1][1]=tt[3];
            }
#pragma unroll
            for(int ni=0;ni<8;ni++) mma16(o[ni], pf[kg2], bf[ni]);
        }
        __syncthreads();
        if(jt+3 < 32){
            load_tile_async_h<64>(kt + sl*2048, kg + (size_t)(64*(jt+3))*HD, HD, 0, tid);
            load_tile_async_h<64>(vt + sl*2048, vg, SS, 64*(jt+3), tid);
        }
        CP_COMMIT();
        sl = (sl==2) ? 0 : sl+1;
    }

    // epilogue
    const float il_lo = 1.f/l_lo, il_hi = 1.f/l_hi;
#pragma unroll
    for(int ni=0;ni<8;ni++){
        const int d = 8*ni + 2*t;
        *(__half2*)(g_ctx + (((size_t)n*BB + b)*SS + r_lo)*HH + h*HD + d)
            = __floats2half2_rn(o[ni][0]*il_lo, o[ni][1]*il_lo);
        *(__half2*)(g_ctx + (((size_t)n*BB + b)*SS + r_hi)*HH + h*HD + d)
            = __floats2half2_rn(o[ni][2]*il_hi, o[ni][3]*il_hi);
    }
    if(t==0){
        const size_t a = ((size_t)n*24 + bh)*SS;
        g_stm[a + r_lo] = m_lo; g_sti[a + r_lo] = il_lo;
        g_stm[a + r_hi] = m_hi; g_sti[a + r_hi] = il_hi;
    }
}

// ---------------------------------------------------------------------------
// K3: flash_b — n=2 coupled path. Uses stored s0',s1' (no QK recompute for
// n=0,1). 64-wide tiles, 3-stage pipeline, split-j: grid (16, 24, 2).
// Emits partial (o, m, l); merged by K4.
// ---------------------------------------------------------------------------
__global__ void __launch_bounds__(256,2) flash_b(const int* __restrict__ mask)
{
    extern __shared__ unsigned smu[];
    float*    maskadd = (float*)smu;            // 2048 floats (pre-scaled by L2E)
    unsigned* qs = smu + 2048;                  // 128x32 (q2)
    unsigned* kt = qs + 4096;                   // 3 x 64x32 (k2)
    unsigned* vt = kt + 3*2048;                 // 3 x 64x32 (v2)

    const int ib = blockIdx.x, bh = blockIdx.y, zh = blockIdx.z;
    const int b = bh/NHEAD;
    const int i0 = ib*128;
    const int tbase = zh*16;                    // first 64-wide j-tile of this half
    const __half* qg = g_q  + ((size_t)2*24 + bh)*SS*HD + (size_t)i0*HD;
    const __half* kg = g_k  + ((size_t)2*24 + bh)*SS*HD;
    const __half* vg = g_vt + ((size_t)2*24 + bh)*SS*HD;

    const int tid = threadIdx.x, w = tid>>5, lane = tid&31;
    const int g = lane>>2, t = lane&3, qq = lane>>3;
    const int rA0 = 16*w + (lane&15), gA = lane>>4;
    const int rB0 = (lane&7) + ((qq>>1)<<3), gB = qq&1;

    for(int j = tid; j < SS; j += 256)
        maskadd[j] = mask[b*SS + j] ? 0.f : -43281.f;

    load_tile_async_h<128>(qs, qg, HD, 0, tid);
    load_tile_async_h<64>(kt, kg + (size_t)(tbase*64)*HD, HD, 0, tid);
    load_tile_async_h<64>(vt, vg, SS, tbase*64, tid);
    CP_COMMIT();
    CP_WAIT(0);
    __syncthreads();

    unsigned qf[4][4];
    const unsigned qBase = (unsigned)__cvta_generic_to_shared(qs);
#pragma unroll
    for(int kg2=0;kg2<4;kg2++){
        const int grp = 2*kg2 + gA;
        ldsm4(qf[kg2], qBase + (rA0<<7) + ((grp ^ (rA0&7))<<4));
    }
    load_tile_async_h<64>(kt + 2048, kg + (size_t)((tbase+1)*64)*HD, HD, 0, tid);
    load_tile_async_h<64>(vt + 2048, vg, SS, (tbase+1)*64, tid);
    CP_COMMIT();
    load_tile_async_h<64>(kt + 4096, kg + (size_t)((tbase+2)*64)*HD, HD, 0, tid);
    load_tile_async_h<64>(vt + 4096, vg, SS, (tbase+2)*64, tid);
    CP_COMMIT();

    // stats from flash_a
    const int r_lo = i0 + 16*w + g, r_hi = r_lo + 8;
    const float m0lo = g_stm[(size_t)(0*24+bh)*SS + r_lo], i0lo = g_sti[(size_t)(0*24+bh)*SS + r_lo];
    const float m0hi = g_stm[(size_t)(0*24+bh)*SS + r_hi], i0hi = g_sti[(size_t)(0*24+bh)*SS + r_hi];
    const float m1lo = g_stm[(size_t)(1*24+bh)*SS + r_lo], i1lo = g_sti[(size_t)(1*24+bh)*SS + r_lo];
    const float m1hi = g_stm[(size_t)(1*24+bh)*SS + r_hi], i1hi = g_sti[(size_t)(1*24+bh)*SS + r_hi];
    const __half2 hm0lo = __float2half2_rn(m0lo), hm0hi = __float2half2_rn(m0hi);
    const __half2 hm1lo = __float2half2_rn(m1lo), hm1hi = __float2half2_rn(m1hi);
    const __half2 c0lo = __float2half2_rn(HC*i0lo), c0hi = __float2half2_rn(HC*i0hi);
    const __half2 c1lo = __float2half2_rn(HC*i1lo), c1hi = __float2half2_rn(HC*i1hi);
    const __half* s0_lo = g_sl + (((size_t)0*24 + bh)*SS + r_lo)*SS;
    const __half* s0_hi = g_sl + (((size_t)0*24 + bh)*SS + r_hi)*SS;
    const __half* s1_lo = g_sl + (((size_t)1*24 + bh)*SS + r_lo)*SS;
    const __half* s1_hi = g_sl + (((size_t)1*24 + bh)*SS + r_hi)*SS;

    const unsigned kBase = (unsigned)__cvta_generic_to_shared(kt);
    const unsigned vBase = (unsigned)__cvta_generic_to_shared(vt);
    const unsigned ones2[2] = {0x3C003C00u, 0x3C003C00u};

    float o[8][4] = {};
    float m2_lo=-1e30f, m2_hi=-1e30f, l2_lo=0.f, l2_hi=0.f;

    int sl = 0;
#pragma unroll 1
    for(int lt=0; lt<16; lt++){
        const int jt = tbase + lt;
        if(lt >= 13) { CP_WAIT(0); } else { CP_WAIT(2); }
        __syncthreads();
        const unsigned kB = kBase + sl*8192;
        const unsigned vB = vBase + sl*8192;

        // QK^T for s2
        float s[8][4] = {};
#pragma unroll
        for(int ks=0;ks<4;ks++){
            unsigned bf[8][2];
#pragma unroll
            for(int np=0;np<4;np++){
                const int row = rB0 + np*16;
                unsigned tt[4];
                ldsm4(tt, kB + (row<<7) + (((2*ks+gB) ^ (row&7))<<4));
                bf[2*np][0]=tt[0]; bf[2*np][1]=tt[1];
                bf[2*np+1][0]=tt[2]; bf[2*np+1][1]=tt[3];
            }
#pragma unroll
            for(int ni=0;ni<8;ni++) mma16(s[ni], qf[ks], bf[ni]);
        }
        // build t: p_a, p_o from stored logits + flash_a stats, add to s2
        const int jb = jt*64;
        __half2 tl[8], th[8];
#pragma unroll
        for(int ni=0;ni<8;ni++){
            const int jo = jb + 8*ni + 2*t;
            __half2 a_lo = *(const __half2*)(s0_lo + jo);
            __half2 a_hi = *(const __half2*)(s0_hi + jo);
            __half2 o_lo = *(const __half2*)(s1_lo + jo);
            __half2 o_hi = *(const __half2*)(s1_hi + jo);
            __half2 dalo = __hsub2(a_lo, hm0lo), dahi = __hsub2(a_hi, hm0hi);
            __half2 dolo = __hsub2(o_lo, hm1lo), dohi = __hsub2(o_hi, hm1hi);
            unsigned ealo = h2ex2(*(unsigned*)&dalo);
            unsigned eahi = h2ex2(*(unsigned*)&dahi);
            unsigned eolo = h2ex2(*(unsigned*)&dolo);
            unsigned eohi = h2ex2(*(unsigned*)&dohi);
            float2 mk = *(const float2*)&maskadd[jo];
            __half2 s2lo = __floats2half2_rn(fmaf(s[ni][0],SCALE2,mk.x),
                                             fmaf(s[ni][1],SCALE2,mk.y));
            __half2 s2hi = __floats2half2_rn(fmaf(s[ni][2],SCALE2,mk.x),
                                             fmaf(s[ni][3],SCALE2,mk.y));
            tl[ni] = __hfma2(*(__half2*)&ealo, c0lo, __hfma2(*(__half2*)&eolo, c1lo, s2lo));
            th[ni] = __hfma2(*(__half2*)&eahi, c0hi, __hfma2(*(__half2*)&eohi, c1hi, s2hi));
        }
        // row max over t (half2 tree, then fp32 shuffles)
        __half2 hmlo = __hmax2(__hmax2(__hmax2(tl[0],tl[1]), __hmax2(tl[2],tl[3])),
                               __hmax2(__hmax2(tl[4],tl[5]), __hmax2(tl[6],tl[7])));
        __half2 hmhi = __hmax2(__hmax2(__hmax2(th[0],th[1]), __hmax2(th[2],th[3])),
                               __hmax2(__hmax2(th[4],th[5]), __hmax2(th[6],th[7])));
        float mx_lo = fmaxf(__low2float(hmlo), __high2float(hmlo));
        float mx_hi = fmaxf(__low2float(hmhi), __high2float(hmhi));
        mx_lo = fmaxf(mx_lo, __shfl_xor_sync(0xffffffffu, mx_lo, 1));
        mx_lo = fmaxf(mx_lo, __shfl_xor_sync(0xffffffffu, mx_lo, 2));
        mx_hi = fmaxf(mx_hi, __shfl_xor_sync(0xffffffffu, mx_hi, 1));
        mx_hi = fmaxf(mx_hi, __shfl_xor_sync(0xffffffffu, mx_hi, 2));
        const float mn_lo = fmaxf(m2_lo, mx_lo), mn_hi = fmaxf(m2_hi, mx_hi);
        const float f_lo = ex2(m2_lo - mn_lo), f_hi = ex2(m2_hi - mn_hi);
        m2_lo = mn_lo; m2_hi = mn_hi;

        const __half2 hm2lo = __float2half2_rn(m2_lo), hm2hi = __float2half2_rn(m2_hi);
        unsigned pf[4][4];
#pragma unroll
        for(int ni=0;ni<8;ni++){
            __half2 dlo = __hsub2(tl[ni], hm2lo);
            __half2 dhi = __hsub2(th[ni], hm2hi);
            pf[ni>>1][(ni&1)*2+0] = h2ex2(*(unsigned*)&dlo);
            pf[ni>>1][(ni&1)*2+1] = h2ex2(*(unsigned*)&dhi);
        }
        float ls[4] = {};
#pragma unroll
        for(int kg2=0;kg2<4;kg2++) mma16(ls, pf[kg2], ones2);
        l2_lo = l2_lo*f_lo + ls[0];
        l2_hi = l2_hi*f_hi + ls[2];
        if(__any_sync(0xffffffffu, (f_lo < 1.f) | (f_hi < 1.f))){
#pragma unroll
            for(int ni=0;ni<8;ni++){
                o[ni][0]*=f_lo; o[ni][1]*=f_lo; o[ni][2]*=f_hi; o[ni][3]*=f_hi;
            }
        }
        // PV with V2
#pragma unroll
        for(int kg2=0;kg2<4;kg2++){
            unsigned bf[8][2];
#pragma unroll
            for(int np=0;np<4;np++){
                const int row = rB0 + np*16;
                unsigned tt[4];
                ldsm4(tt, vB + (row<<7) + (((2*kg2+gB) ^ (row&7))<<4));
                bf[2*np][0]=tt[0]; bf[2*np][1]=tt[1];
                bf[2*np+1][0]=tt[2]; bf[2*np+1][1]=tt[3];
            }
#pragma unroll
            for(int ni=0;ni<8;ni++) mma16(o[ni], pf[kg2], bf[ni]);
        }
        __syncthreads();
        if(lt+3 < 16){
            load_tile_async_h<64>(kt + sl*2048, kg + (size_t)(64*(jt+3))*HD, HD, 0, tid);
            load_tile_async_h<64>(vt + sl*2048, vg, SS, 64*(jt+3), tid);
        }
        CP_COMMIT();
        sl = (sl==2) ? 0 : sl+1;
    }

    // store partial (o unnormalized, m, l)
    const size_t base = ((size_t)zh*24 + bh)*SS;
#pragma unroll
    for(int ni=0;ni<8;ni++){
        const int d = 8*ni + 2*t;
        float2 plo; plo.x = o[ni][0]; plo.y = o[ni][1];
        float2 phi; phi.x = o[ni][2]; phi.y = o[ni][3];
        *(float2*)(g_po + (base + r_lo)*HD + d) = plo;
        *(float2*)(g_po + (base + r_hi)*HD + d) = phi;
    }
    if(t==0){
        g_pm[base + r_lo] = m2_lo; g_pl[base + r_lo] = l2_lo;
        g_pm[base + r_hi] = m2_hi; g_pl[base + r_hi] = l2_hi;
    }
}

// ---------------------------------------------------------------------------
// K4: merge_b — combine the two j-half partials into ctx (n=2).
// ---------------------------------------------------------------------------
__global__ void __launch_bounds__(256) merge_b()
{
    const int idx = blockIdx.x*256 + threadIdx.x;
    const int grp = idx & 7;
    const int rowg = idx >> 3;
    const int bh = rowg >> 11, r = rowg & 2047;
    const int b = bh/NHEAD, h = bh%NHEAD;

    const float m0 = g_pm[rowg], m1 = g_pm[24*SS + rowg];
    const float l0 = g_pl[rowg], l1 = g_pl[24*SS + rowg];
    const float m = fmaxf(m0, m1);
    const float f0 = ex2(m0 - m), f1 = ex2(m1 - m);
    const float il = 1.f/(l0*f0 + l1*f1);
    const float c0 = f0*il, c1 = f1*il;

    const size_t o0 = (size_t)rowg*HD + grp*8;
    const size_t o1 = (size_t)(24*SS + rowg)*HD + grp*8;
    float4 a0 = *(const float4*)(g_po + o0);
    float4 a1 = *(const float4*)(g_po + o0 + 4);
    float4 b0 = *(const float4*)(g_po + o1);
    float4 b1 = *(const float4*)(g_po + o1 + 4);

    __align__(16) __half2 hh[4];
    hh[0] = __floats2half2_rn(a0.x*c0 + b0.x*c1, a0.y*c0 + b0.y*c1);
    hh[1] = __floats2half2_rn(a0.z*c0 + b0.z*c1, a0.w*c0 + b0.w*c1);
    hh[2] = __floats2half2_rn(a1.x*c0 + b1.x*c1, a1.y*c0 + b1.y*c1);
    hh[3] = __floats2half2_rn(a1.z*c0 + b1.z*c1, a1.w*c0 + b1.w*c1);
    *(uint4*)(g_ctx + (((size_t)2*BB + b)*SS + r)*HH + h*HD + grp*8) = *(uint4*)hh;
}

// ---------------------------------------------------------------------------
// K5: output projection.  Block 128x128. grid (6, 32, 3). fp32 out + bias.
// ---------------------------------------------------------------------------
__global__ void __launch_bounds__(256,2) outproj_tc(
    const float* __restrict__ bo, float* __restrict__ out)
{
    extern __shared__ unsigned smu[];
    unsigned* sA = smu;
    unsigned* sB = smu + 2*128*32;
    const int n = blockIdx.z;
    const __half* X   = g_ctx + (size_t)n*MM*HH;
    const __half* Wt  = g_wt + (size_t)(9+n)*HH*HH;
    const float* bias = bo + (size_t)n*HH;
    float* O = out + (size_t)n*MM*HH;

    const int m0 = blockIdx.y*128, e0 = blockIdx.x*128;
    const int tid = threadIdx.x, wid = tid>>5, lane = tid&31;
    const int gid = lane>>2, tig = lane&3;
    const int wm = wid & 1, wn = wid >> 1;

    float acc[4][4][4] = {};
    gemm_body_h<HH,128,128>(sA, sB, X + (size_t)m0*HH, HH, Wt + (size_t)e0*HH, HH,
                            tid, wm*64, wn*32, gid, tig, acc);

#pragma unroll
    for(int mi=0;mi<4;mi++)
#pragma unroll
    for(int ni=0;ni<4;ni++){
        const int e = e0 + wn*32 + ni*8 + 2*tig;
        const float2 b2 = *(const float2*)(bias + e);
#pragma unroll
        for(int h2=0;h2<2;h2++){
            int m = m0 + wm*64 + mi*16 + gid + h2*8;
            float2 oo; oo.x = acc[mi][ni][h2*2+0] + b2.x; oo.y = acc[mi][ni][h2*2+1] + b2.y;
            *(float2*)(O + (size_t)m*HH + e) = oo;
        }
    }
}

// ---------------------------------------------------------------------------
// Launch
// ---------------------------------------------------------------------------
extern "C" void kernel_launch(void* const* d_in, const int* in_sizes, int n_in,
                              void* d_out, int out_size)
{
    (void)in_sizes; (void)n_in; (void)out_size;
    const float* hidden = (const float*)d_in[0];
    // d_in[1] aspect_weights, d_in[2] opinion_weights: per-query-row biases cancel in softmax
    const int*   mask   = (const int*)  d_in[3];
    const float* Wq = (const float*)d_in[4];  const float* bq = (const float*)d_in[5];
    const float* Wk = (const float*)d_in[6];  const float* bk = (const float*)d_in[7];
    const float* Wv = (const float*)d_in[8];  const float* bv = (const float*)d_in[9];
    const float* Wo = (const float*)d_in[10]; const float* bo = (const float*)d_in[11];
    float* out = (float*)d_out;

    const int smemAB = (2*128*32 + 2*128*32) * 4;              // 64 KB (proj/outproj)
    const int smemFA = (2048 + 4096 + 3*2048 + 3*2048) * 4;    // 72 KB (flash_a & flash_b)
    cudaFuncSetAttribute(proj_tc,    cudaFuncAttributeMaxDynamicSharedMemorySize, smemAB);
    cudaFuncSetAttribute(flash_a,    cudaFuncAttributeMaxDynamicSharedMemorySize, smemFA);
    cudaFuncSetAttribute(flash_b,    cudaFuncAttributeMaxDynamicSharedMemorySize, smemFA);
    cudaFuncSetAttribute(outproj_tc, cudaFuncAttributeMaxDynamicSharedMemorySize, smemAB);

    conv_hidden<<<dim3(MM*HH/2048), 256>>>(hidden);
    transpose_w<<<dim3(24,24,12), 256>>>(Wq, Wk, Wv, Wo);
    proj_tc    <<<dim3(6, 32, 9), 256, smemAB>>>(bq, bk, bv);
    flash_a    <<<dim3(16, 24, 2), 256, smemFA>>>(mask);
    flash_b    <<<dim3(16, 24, 2), 256, smemFA>>>(mask);
    merge_b    <<<dim3(1536), 256>>>();
    outproj_tc <<<dim3(6, 32, 3), 256, smemAB>>>(bo, out);
}

// round 17
// speedup vs baseline: 1.1812x; 1.1812x over previous
#include <cuda_runtime.h>
#include <cuda_fp16.h>
#include <cstddef>

// Problem constants
#define BB 2
#define SS 2048
#define HH 768
#define NHEAD 12
#define HD 64
#define MM (BB*SS)          // 4096
#define SCALE 0.125f        // HD^-0.5
#define L2E 1.4426950408889634f
#define SCALE2 (SCALE*L2E)  // fold into logit: s' = s*log2(e)
#define HC (0.5f*L2E)

// ---------------------------------------------------------------------------
// Device scratch
// ---------------------------------------------------------------------------
__device__ __half g_hh[(size_t)MM*HH];                 // hidden in fp16
__device__ __half g_q [(size_t)3*BB*NHEAD*SS*HD];
__device__ __half g_k [(size_t)3*BB*NHEAD*SS*HD];
__device__ __half g_vt[(size_t)3*BB*NHEAD*SS*HD];      // V transposed: [n][bh][d][s]
__device__ __half g_ctx[(size_t)3*MM*HH];
__device__ __half g_wt[(size_t)12*HH*HH];              // transposed fp16 weights
__device__ float  g_stm[(size_t)2*24*SS];              // row max (log2 domain) n=0,1
__device__ float  g_sti[(size_t)2*24*SS];              // row 1/sum n=0,1
// flash_b split-j partials (2 halves)
__device__ float  g_po[(size_t)2*24*SS*HD];            // partial o (unnormalized)
__device__ float  g_pm[(size_t)2*24*SS];               // partial row max (log2)
__device__ float  g_pl[(size_t)2*24*SS];               // partial row sum

// ---------------------------------------------------------------------------
// fp16 mma helpers (m16n8k16, fp32 accumulate)
// ---------------------------------------------------------------------------
__device__ __forceinline__ void mma16(float c[4], const unsigned a[4], const unsigned b[2]){
    asm volatile("mma.sync.aligned.m16n8k16.row.col.f32.f16.f16.f32 "
        "{%0,%1,%2,%3},{%4,%5,%6,%7},{%8,%9},{%0,%1,%2,%3};"
        : "+f"(c[0]),"+f"(c[1]),"+f"(c[2]),"+f"(c[3])
        : "r"(a[0]),"r"(a[1]),"r"(a[2]),"r"(a[3]),"r"(b[0]),"r"(b[1]));
}
__device__ __forceinline__ void ldsm4(unsigned r[4], unsigned saddr){
    asm volatile("ldmatrix.sync.aligned.m8n8.x4.shared.b16 {%0,%1,%2,%3}, [%4];"
        : "=r"(r[0]),"=r"(r[1]),"=r"(r[2]),"=r"(r[3]) : "r"(saddr));
}
__device__ __forceinline__ unsigned packh2(float a, float b){
    __half2 h = __floats2half2_rn(a, b);
    return *reinterpret_cast<unsigned*>(&h);
}
// raw MUFU.EX2 fp32
__device__ __forceinline__ float ex2(float x){
    float r; asm("ex2.approx.f32 %0, %1;" : "=f"(r) : "f"(x)); return r;
}
// packed half2 exp2 on MUFU (2 values / instruction)
__device__ __forceinline__ unsigned h2ex2(unsigned x){
    unsigned r; asm("ex2.approx.f16x2 %0, %1;" : "=r"(r) : "r"(x)); return r;
}

// cp.async 16B (8 halfs)
__device__ __forceinline__ void cp16h(unsigned* s, const __half* g){
    unsigned sa = (unsigned)__cvta_generic_to_shared(s);
    asm volatile("cp.async.cg.shared.global [%0], [%1], 16;" :: "r"(sa), "l"(g));
}
#define CP_COMMIT()   asm volatile("cp.async.commit_group;")
#define CP_WAIT(N)    asm volatile("cp.async.wait_group %0;" :: "n"(N))

// Async load of a [ROWS x 64] k-major half tile (row stride ld halfs) into smem.
template<int ROWS>
__device__ __forceinline__ void load_tile_async_h(unsigned* s, const __half* __restrict__ g,
                                                  size_t ld, int k0, int tid){
#pragma unroll
    for(int i=0;i<ROWS*8/256;i++){
        int idx = i*256 + tid;
        int row = idx>>3, c = idx&7;
        cp16h(s + (row<<5) + ((c ^ (row&7))<<2), g + (size_t)row*ld + k0 + 8*c);
    }
}
// 32-half k-window variant (rows still 32 uints wide; groups 0..3 used).
template<int ROWS>
__device__ __forceinline__ void load_tile32_async_h(unsigned* s, const __half* __restrict__ g,
                                                    size_t ld, int k0, int tid){
#pragma unroll
    for(int i=0;i<ROWS*4/256;i++){
        int idx = i*256 + tid;
        int row = idx>>2, c = idx&3;
        cp16h(s + (row<<5) + ((c ^ (row&7))<<2), g + (size_t)row*ld + k0 + 8*c);
    }
}

// One BK=64 block-step via ldmatrix. Warp tile = MI m16 x NI n8 (NI even).
template<int MI,int NI>
__device__ __forceinline__ void mma_block_h(const unsigned* sA, const unsigned* sB,
        int wm_base, int wn_base, int gid, int tig, float acc[MI][NI][4]){
    (void)gid; (void)tig;
    const int lane = threadIdx.x & 31;
    const unsigned baseA = (unsigned)__cvta_generic_to_shared(sA);
    const unsigned baseB = (unsigned)__cvta_generic_to_shared(sB);
    const int rA0 = wm_base + (lane & 15);
    const int gA  = lane >> 4;
    const int q   = lane >> 3;
    const int rB0 = wn_base + (lane & 7) + ((q >> 1) << 3);
    const int gB  = q & 1;
#pragma unroll
    for(int ks=0;ks<4;ks++){
        unsigned af[MI][4], bf[NI][2];
#pragma unroll
        for(int mi=0;mi<MI;mi++){
            const int row = rA0 + mi*16;
            const int grp = 2*ks + gA;
            ldsm4(af[mi], baseA + (row<<7) + ((grp ^ (row&7))<<4));
        }
#pragma unroll
        for(int np=0;np<NI/2;np++){
            const int row = rB0 + np*16;
            const int grp = 2*ks + gB;
            unsigned t[4];
            ldsm4(t, baseB + (row<<7) + ((grp ^ (row&7))<<4));
            bf[np*2  ][0]=t[0]; bf[np*2  ][1]=t[1];
            bf[np*2+1][0]=t[2]; bf[np*2+1][1]=t[3];
        }
#pragma unroll
        for(int mi=0;mi<MI;mi++)
#pragma unroll
            for(int ni=0;ni<NI;ni++)
                mma16(acc[mi][ni], af[mi], bf[ni]);
    }
}

// ---------------------------------------------------------------------------
// K0: convert hidden fp32 -> fp16.
// ---------------------------------------------------------------------------
__global__ void __launch_bounds__(256) conv_hidden(const float* __restrict__ X)
{
    size_t i = ((size_t)blockIdx.x*256 + threadIdx.x)*8;
    float4 a = *(const float4*)(X + i);
    float4 b = *(const float4*)(X + i + 4);
    __align__(16) __half2 h[4];
    h[0] = __floats2half2_rn(a.x, a.y);
    h[1] = __floats2half2_rn(a.z, a.w);
    h[2] = __floats2half2_rn(b.x, b.y);
    h[3] = __floats2half2_rn(b.z, b.w);
    *(uint4*)(g_hh + i) = *(uint4*)h;
}

// ---------------------------------------------------------------------------
// K0a: transpose + fp16-convert the 12 weight matrices [h][e] -> g_wt[mat][e][h]
// ---------------------------------------------------------------------------
__global__ void __launch_bounds__(256) transpose_w(
    const float* __restrict__ Wq, const float* __restrict__ Wk,
    const float* __restrict__ Wv, const float* __restrict__ Wo)
{
    __shared__ __half t[32][33];
    const int mat = blockIdx.z;
    const float* src = (mat<3?Wq:mat<6?Wk:mat<9?Wv:Wo) + (size_t)(mat%3)*HH*HH;
    __half* dst = g_wt + (size_t)mat*HH*HH;
    const int x0 = blockIdx.x*32, y0 = blockIdx.y*32;
    const int tx = threadIdx.x & 31, ty = threadIdx.x >> 5;
#pragma unroll
    for(int r=0;r<4;r++) t[ty+8*r][tx] = __float2half_rn(src[(size_t)(y0+ty+8*r)*HH + x0 + tx]);
    __syncthreads();
#pragma unroll
    for(int r=0;r<4;r++) dst[(size_t)(x0+ty+8*r)*HH + y0 + tx] = t[tx][ty+8*r];
}

// ---------------------------------------------------------------------------
// Generic double-buffered fp16 GEMM body (proj/outproj): MI=NI=4, BK=64.
// ---------------------------------------------------------------------------
template<int KTOT,int AR,int BR>
__device__ __forceinline__ void gemm_body_h(
    unsigned* sA, unsigned* sB,
    const __half* __restrict__ A, size_t lda,
    const __half* __restrict__ B, size_t ldb,
    int tid, int wm_base, int wn_base, int gid, int tig,
    float acc[4][4][4])
{
    load_tile_async_h<AR>(sA, A, lda, 0, tid);
    load_tile_async_h<BR>(sB, B, ldb, 0, tid);
    CP_COMMIT();
    const int nk = KTOT/64;
#pragma unroll 1
    for(int kt=0; kt<nk; kt++){
        const int cur = kt & 1, nxt = cur ^ 1;
        if(kt+1 < nk){
            load_tile_async_h<AR>(sA + nxt*AR*32, A, lda, (kt+1)*64, tid);
            load_tile_async_h<BR>(sB + nxt*BR*32, B, ldb, (kt+1)*64, tid);
        }
        CP_COMMIT();
        CP_WAIT(1);
        __syncthreads();
        mma_block_h<4,4>(sA + cur*AR*32, sB + cur*BR*32, wm_base, wn_base, gid, tig, acc);
        __syncthreads();
    }
}

// ---------------------------------------------------------------------------
// K1: QKV projection.  Block 128x128. grid (6, 32, 9). fp16 in/out.
// t==2 (V): stage in smem and write DIRECTLY TRANSPOSED into g_vt.
// ---------------------------------------------------------------------------
__global__ void __launch_bounds__(256,2) proj_tc(
    const float* __restrict__ bq, const float* __restrict__ bk, const float* __restrict__ bv)
{
    extern __shared__ unsigned smu[];
    unsigned* sA = smu;
    unsigned* sB = smu + 2*128*32;
    const int z = blockIdx.z, n = z%3, t = z/3;
    const __half* Wt  = g_wt + (size_t)(t*3+n)*HH*HH;
    const float* bias = (t==0?bq:(t==1?bk:bv)) + (size_t)n*HH;

    const int m0 = blockIdx.y*128, e0 = blockIdx.x*128;
    const int tid = threadIdx.x, wid = tid>>5, lane = tid&31;
    const int gid = lane>>2, tig = lane&3;
    const int wm = wid & 1, wn = wid >> 1;

    float acc[4][4][4] = {};
    gemm_body_h<HH,128,128>(sA, sB, g_hh + (size_t)m0*HH, HH, Wt + (size_t)e0*HH, HH,
                            tid, wm*64, wn*32, gid, tig, acc);

    if(t < 2){
        __half* O = (t==0 ? g_q : g_k) + (size_t)n*BB*NHEAD*SS*HD;
#pragma unroll
        for(int mi=0;mi<4;mi++)
#pragma unroll
        for(int ni=0;ni<4;ni++){
            const int e = e0 + wn*32 + ni*8 + 2*tig;
            const float2 b2 = *(const float2*)(bias + e);
            const int head = e>>6, d = e&63;
#pragma unroll
            for(int h2=0;h2<2;h2++){
                int m = m0 + wm*64 + mi*16 + gid + h2*8;
                int b = m>>11, s = m & (SS-1);
                __half2 o = __floats2half2_rn(acc[mi][ni][h2*2+0] + b2.x,
                                              acc[mi][ni][h2*2+1] + b2.y);
                *(__half2*)(O + (((size_t)b*NHEAD + head)*SS + s)*HD + d) = o;
            }
        }
    } else {
        __half* st = (__half*)smu;   // 128*136 halfs
#pragma unroll
        for(int mi=0;mi<4;mi++)
#pragma unroll
        for(int ni=0;ni<4;ni++){
            const int el = wn*32 + ni*8 + 2*tig;
            const float2 b2 = *(const float2*)(bias + e0 + el);
#pragma unroll
            for(int h2=0;h2<2;h2++){
                const int ml = wm*64 + mi*16 + gid + h2*8;
                st[(el  )*136 + ml] = __float2half_rn(acc[mi][ni][h2*2+0] + b2.x);
                st[(el+1)*136 + ml] = __float2half_rn(acc[mi][ni][h2*2+1] + b2.y);
            }
        }
        __syncthreads();
        const int b = m0 >> 11, sb = m0 & (SS-1);
#pragma unroll
        for(int r=0;r<8;r++){
            const int idx = r*256 + tid;
            const int el = idx >> 4, c8 = (idx & 15)*8;
            const int head = 2*blockIdx.x + (el>>6), d = el & 63;
            uint4 v = *(uint4*)&st[el*136 + c8];
            *(uint4*)(g_vt + ((size_t)(n*24 + b*NHEAD + head))*SS*HD
                           + (size_t)d*SS + sb + c8) = v;
        }
    }
}

// ---------------------------------------------------------------------------
// K2: flash_a — fused QK^T + online softmax + PV for n = 0,1. (3-stage)
// Uniform fast path when the mask row is all-ones (mask math folds away).
// grid (16 i-stripes, 24 bh, 2 n), 256 threads.
// ---------------------------------------------------------------------------
__global__ void __launch_bounds__(256,2) flash_a(const int* __restrict__ mask)
{
    extern __shared__ unsigned smu[];
    float*    maskadd = (float*)smu;            // 2048 floats (pre-scaled by L2E)
    unsigned* qs = smu + 2048;                  // 128x32
    unsigned* kt = qs + 4096;                   // 3 x 64x32
    unsigned* vt = kt + 3*2048;                 // 3 x 64x32

    const int ib = blockIdx.x, bh = blockIdx.y, n = blockIdx.z;
    const int b = bh/NHEAD, h = bh%NHEAD;
    const int i0 = ib*128;
    const __half* qg = g_q  + ((size_t)n*24 + bh)*SS*HD + (size_t)i0*HD;
    const __half* kg = g_k  + ((size_t)n*24 + bh)*SS*HD;
    const __half* vg = g_vt + ((size_t)n*24 + bh)*SS*HD;

    const int tid = threadIdx.x, w = tid>>5, lane = tid&31;
    const int g = lane>>2, t = lane&3, qq = lane>>3;
    const int rA0 = 16*w + (lane&15), gA = lane>>4;
    const int rB0 = (lane&7) + ((qq>>1)<<3), gB = qq&1;

    int la = 1;
    for(int j = tid; j < SS; j += 256){
        const int mv = mask[b*SS + j];
        maskadd[j] = mv ? 0.f : -43281.f;   // -30000 * log2(e)
        la &= (mv != 0);
    }
    const int allone = __syncthreads_and(la);

    load_tile_async_h<128>(qs, qg, HD, 0, tid);
    load_tile_async_h<64>(kt, kg, HD, 0, tid);
    load_tile_async_h<64>(vt, vg, SS, 0, tid);
    CP_COMMIT();
    CP_WAIT(0);
    __syncthreads();

    unsigned qf[4][4];
    const unsigned qBase = (unsigned)__cvta_generic_to_shared(qs);
#pragma unroll
    for(int kg2=0;kg2<4;kg2++){
        const int grp = 2*kg2 + gA;
        ldsm4(qf[kg2], qBase + (rA0<<7) + ((grp ^ (rA0&7))<<4));
    }
    load_tile_async_h<64>(kt + 2048, kg + (size_t)64*HD, HD, 0, tid);
    load_tile_async_h<64>(vt + 2048, vg, SS, 64, tid);
    CP_COMMIT();
    load_tile_async_h<64>(kt + 4096, kg + (size_t)128*HD, HD, 0, tid);
    load_tile_async_h<64>(vt + 4096, vg, SS, 128, tid);
    CP_COMMIT();

    float o[8][4] = {};
    float m_lo=-1e30f, m_hi=-1e30f, l_lo=0.f, l_hi=0.f;
    const unsigned kBase = (unsigned)__cvta_generic_to_shared(kt);
    const unsigned vBase = (unsigned)__cvta_generic_to_shared(vt);
    const unsigned ones2[2] = {0x3C003C00u, 0x3C003C00u};

    int sl = 0;
#pragma unroll 1
    for(int jt=0; jt<32; jt++){
        CP_WAIT(2);
        __syncthreads();
        const unsigned kB = kBase + sl*8192;
        const unsigned vB = vBase + sl*8192;

        // QK^T
        float s[8][4] = {};
#pragma unroll
        for(int ks=0;ks<4;ks++){
            unsigned bf[8][2];
#pragma unroll
            for(int np=0;np<4;np++){
                const int row = rB0 + np*16;
                unsigned tt[4];
                ldsm4(tt, kB + (row<<7) + (((2*ks+gB) ^ (row&7))<<4));
                bf[2*np][0]=tt[0]; bf[2*np][1]=tt[1];
                bf[2*np+1][0]=tt[2]; bf[2*np+1][1]=tt[3];
            }
#pragma unroll
            for(int ni=0;ni<8;ni++) mma16(s[ni], qf[ks], bf[ni]);
        }

        unsigned pf[4][4];
        float f_lo, f_hi;
        if(allone){
            // FAST: no mask math. max over raw s, scale commutes with max.
            float mx_lo=-1e30f, mx_hi=-1e30f;
#pragma unroll
            for(int ni=0;ni<8;ni++){
                mx_lo = fmaxf(mx_lo, fmaxf(s[ni][0], s[ni][1]));
                mx_hi = fmaxf(mx_hi, fmaxf(s[ni][2], s[ni][3]));
            }
            mx_lo = fmaxf(mx_lo, __shfl_xor_sync(0xffffffffu, mx_lo, 1));
            mx_lo = fmaxf(mx_lo, __shfl_xor_sync(0xffffffffu, mx_lo, 2));
            mx_hi = fmaxf(mx_hi, __shfl_xor_sync(0xffffffffu, mx_hi, 1));
            mx_hi = fmaxf(mx_hi, __shfl_xor_sync(0xffffffffu, mx_hi, 2));
            const float mn_lo = fmaxf(m_lo, mx_lo*SCALE2);
            const float mn_hi = fmaxf(m_hi, mx_hi*SCALE2);
            f_lo = ex2(m_lo - mn_lo); f_hi = ex2(m_hi - mn_hi);
            m_lo = mn_lo; m_hi = mn_hi;
            // scale+shift fused into the pack
#pragma unroll
            for(int ni=0;ni<8;ni++){
                pf[ni>>1][(ni&1)*2+0] = h2ex2(packh2(fmaf(s[ni][0],SCALE2,-m_lo),
                                                     fmaf(s[ni][1],SCALE2,-m_lo)));
                pf[ni>>1][(ni&1)*2+1] = h2ex2(packh2(fmaf(s[ni][2],SCALE2,-m_hi),
                                                     fmaf(s[ni][3],SCALE2,-m_hi)));
            }
        } else {
            // GENERAL: scale+mask (log2 domain) + row max (fp32)
            const int jb = jt*64;
            float mx_lo=-1e30f, mx_hi=-1e30f;
#pragma unroll
            for(int ni=0;ni<8;ni++){
                float2 mk = *(const float2*)&maskadd[jb + 8*ni + 2*t];
                s[ni][0] = fmaf(s[ni][0], SCALE2, mk.x);
                s[ni][1] = fmaf(s[ni][1], SCALE2, mk.y);
                s[ni][2] = fmaf(s[ni][2], SCALE2, mk.x);
                s[ni][3] = fmaf(s[ni][3], SCALE2, mk.y);
                mx_lo = fmaxf(mx_lo, fmaxf(s[ni][0], s[ni][1]));
                mx_hi = fmaxf(mx_hi, fmaxf(s[ni][2], s[ni][3]));
            }
            mx_lo = fmaxf(mx_lo, __shfl_xor_sync(0xffffffffu, mx_lo, 1));
            mx_lo = fmaxf(mx_lo, __shfl_xor_sync(0xffffffffu, mx_lo, 2));
            mx_hi = fmaxf(mx_hi, __shfl_xor_sync(0xffffffffu, mx_hi, 1));
            mx_hi = fmaxf(mx_hi, __shfl_xor_sync(0xffffffffu, mx_hi, 2));
            const float mn_lo = fmaxf(m_lo, mx_lo), mn_hi = fmaxf(m_hi, mx_hi);
            f_lo = ex2(m_lo - mn_lo); f_hi = ex2(m_hi - mn_hi);
            m_lo = mn_lo; m_hi = mn_hi;
#pragma unroll
            for(int ni=0;ni<8;ni++){
                pf[ni>>1][(ni&1)*2+0] = h2ex2(packh2(s[ni][0]-m_lo, s[ni][1]-m_lo));
                pf[ni>>1][(ni&1)*2+1] = h2ex2(packh2(s[ni][2]-m_hi, s[ni][3]-m_hi));
            }
        }
        // exact row sums of the quantized p via ones-mma
        float ls[4] = {};
#pragma unroll
        for(int kg2=0;kg2<4;kg2++) mma16(ls, pf[kg2], ones2);
        l_lo = l_lo*f_lo + ls[0];
        l_hi = l_hi*f_hi + ls[2];
        if(__any_sync(0xffffffffu, (f_lo < 1.f) | (f_hi < 1.f))){
#pragma unroll
            for(int ni=0;ni<8;ni++){
                o[ni][0]*=f_lo; o[ni][1]*=f_lo; o[ni][2]*=f_hi; o[ni][3]*=f_hi;
            }
        }
        // PV
#pragma unroll
        for(int kg2=0;kg2<4;kg2++){
            unsigned bf[8][2];
#pragma unroll
            for(int np=0;np<4;np++){
                const int row = rB0 + np*16;
                unsigned tt[4];
                ldsm4(tt, vB + (row<<7) + (((2*kg2+gB) ^ (row&7))<<4));
                bf[2*np][0]=tt[0]; bf[2*np][1]=tt[1];
                bf[2*np+1][0]=tt[2]; bf[2*np+1][1]=tt[3];
            }
#pragma unroll
            for(int ni=0;ni<8;ni++) mma16(o[ni], pf[kg2], bf[ni]);
        }
        __syncthreads();
        if(jt+3 < 32){
            load_tile_async_h<64>(kt + sl*2048, kg + (size_t)(64*(jt+3))*HD, HD, 0, tid);
            load_tile_async_h<64>(vt + sl*2048, vg, SS, 64*(jt+3), tid);
        }
        CP_COMMIT();
        sl = (sl==2) ? 0 : sl+1;
    }

    // epilogue
    const float il_lo = 1.f/l_lo, il_hi = 1.f/l_hi;
    const int r_lo = i0 + 16*w + g, r_hi = r_lo + 8;
#pragma unroll
    for(int ni=0;ni<8;ni++){
        const int d = 8*ni + 2*t;
        *(__half2*)(g_ctx + (((size_t)n*BB + b)*SS + r_lo)*HH + h*HD + d)
            = __floats2half2_rn(o[ni][0]*il_lo, o[ni][1]*il_lo);
        *(__half2*)(g_ctx + (((size_t)n*BB + b)*SS + r_hi)*HH + h*HD + d)
            = __floats2half2_rn(o[ni][2]*il_hi, o[ni][3]*il_hi);
    }
    if(t==0){
        const size_t a = ((size_t)n*24 + bh)*SS;
        g_stm[a + r_lo] = m_lo; g_sti[a + r_lo] = il_lo;
        g_stm[a + r_hi] = m_hi; g_sti[a + r_hi] = il_hi;
    }
}

// ---------------------------------------------------------------------------
// K3: flash_b — n=2 coupled path, SPLIT over j: grid (16, 24, 2).
// Uniform fast path when mask is all-ones. Emits partial (o, m, l).
// ---------------------------------------------------------------------------
__global__ void __launch_bounds__(256,2) flash_b(const int* __restrict__ mask)
{
    extern __shared__ unsigned smu[];
    float*    maskadd = (float*)smu;            // 2048 floats (pre-scaled by L2E)
    unsigned* qs = smu + 2048;                  // 3 x 128x32 (q0,q1,q2)
    unsigned* buf = smu + 2048 + 3*4096;        // 2 stages x (3x 32x32 k + 64x32 vt2)

    const int ib = blockIdx.x, bh = blockIdx.y, zh = blockIdx.z;
    const int b = bh/NHEAD;
    const int i0 = ib*128;
    const int jbase = zh*32;                    // first j-tile of this half
    const __half* q0g = g_q + ((size_t)0*24 + bh)*SS*HD + (size_t)i0*HD;
    const __half* q1g = g_q + ((size_t)1*24 + bh)*SS*HD + (size_t)i0*HD;
    const __half* q2g = g_q + ((size_t)2*24 + bh)*SS*HD + (size_t)i0*HD;
    const __half* k0g = g_k + ((size_t)0*24 + bh)*SS*HD;
    const __half* k1g = g_k + ((size_t)1*24 + bh)*SS*HD;
    const __half* k2g = g_k + ((size_t)2*24 + bh)*SS*HD;
    const __half* v2g = g_vt + ((size_t)2*24 + bh)*SS*HD;

    const int tid = threadIdx.x, w = tid>>5, lane = tid&31;
    const int g = lane>>2, t = lane&3, qq = lane>>3;
    const int rA0 = 16*w + (lane&15), gA = lane>>4;
    const int rB0 = (lane&7) + ((qq>>1)<<3), gB = qq&1;

    int la = 1;
    for(int j = tid; j < SS; j += 256){
        const int mv = mask[b*SS + j];
        maskadd[j] = mv ? 0.f : -43281.f;
        la &= (mv != 0);
    }
    const int allone = __syncthreads_and(la);

    load_tile_async_h<128>(qs,        q0g, HD, 0, tid);
    load_tile_async_h<128>(qs+4096,   q1g, HD, 0, tid);
    load_tile_async_h<128>(qs+8192,   q2g, HD, 0, tid);
    load_tile_async_h<32>(buf,        k0g + (size_t)(jbase*32)*HD, HD, 0, tid);
    load_tile_async_h<32>(buf+1024,   k1g + (size_t)(jbase*32)*HD, HD, 0, tid);
    load_tile_async_h<32>(buf+2048,   k2g + (size_t)(jbase*32)*HD, HD, 0, tid);
    load_tile32_async_h<64>(buf+3072, v2g, SS, jbase*32, tid);
    CP_COMMIT();
    load_tile_async_h<32>(buf+5120,        k0g + (size_t)((jbase+1)*32)*HD, HD, 0, tid);
    load_tile_async_h<32>(buf+5120+1024,   k1g + (size_t)((jbase+1)*32)*HD, HD, 0, tid);
    load_tile_async_h<32>(buf+5120+2048,   k2g + (size_t)((jbase+1)*32)*HD, HD, 0, tid);
    load_tile32_async_h<64>(buf+5120+3072, v2g, SS, (jbase+1)*32, tid);
    CP_COMMIT();

    const int r_lo = i0 + 16*w + g, r_hi = r_lo + 8;
    const float m0lo = g_stm[(size_t)(0*24+bh)*SS + r_lo], i0lo = g_sti[(size_t)(0*24+bh)*SS + r_lo];
    const float m0hi = g_stm[(size_t)(0*24+bh)*SS + r_hi], i0hi = g_sti[(size_t)(0*24+bh)*SS + r_hi];
    const float m1lo = g_stm[(size_t)(1*24+bh)*SS + r_lo], i1lo = g_sti[(size_t)(1*24+bh)*SS + r_lo];
    const float m1hi = g_stm[(size_t)(1*24+bh)*SS + r_hi], i1hi = g_sti[(size_t)(1*24+bh)*SS + r_hi];
    const __half2 c0lo = __float2half2_rn(HC*i0lo), c0hi = __float2half2_rn(HC*i0hi);
    const __half2 c1lo = __float2half2_rn(HC*i1lo), c1hi = __float2half2_rn(HC*i1hi);

    const unsigned qB0 = (unsigned)__cvta_generic_to_shared(qs);
    const unsigned bB  = (unsigned)__cvta_generic_to_shared(buf);
    const unsigned ones2[2] = {0x3C003C00u, 0x3C003C00u};

    float o[8][4] = {};
    float m2_lo=-1e30f, m2_hi=-1e30f, l2_lo=0.f, l2_hi=0.f;

#pragma unroll 1
    for(int lt=0; lt<32; lt++){
        const int jt = jbase + lt;
        if(lt==31) { CP_WAIT(0); } else { CP_WAIT(1); }
        __syncthreads();
        const unsigned st = bB + (lt&1)*20480;

        float s0[4][4] = {}, s1[4][4] = {}, s2[4][4] = {};
#pragma unroll
        for(int ks=0;ks<4;ks++){
            unsigned qa0[4], qa1[4], qa2[4];
            const int grp = 2*ks + gA;
            const unsigned aoff = (rA0<<7) + ((grp ^ (rA0&7))<<4);
            ldsm4(qa0, qB0 + aoff);
            ldsm4(qa1, qB0 + 16384 + aoff);
            ldsm4(qa2, qB0 + 32768 + aoff);
            unsigned b0[4][2], b1[4][2], b2[4][2];
#pragma unroll
            for(int np=0;np<2;np++){
                const int row = rB0 + np*16;
                const unsigned boff = (row<<7) + (((2*ks+gB) ^ (row&7))<<4);
                unsigned tt[4];
                ldsm4(tt, st + boff);
                b0[2*np][0]=tt[0]; b0[2*np][1]=tt[1]; b0[2*np+1][0]=tt[2]; b0[2*np+1][1]=tt[3];
                ldsm4(tt, st + 4096 + boff);
                b1[2*np][0]=tt[0]; b1[2*np][1]=tt[1]; b1[2*np+1][0]=tt[2]; b1[2*np+1][1]=tt[3];
                ldsm4(tt, st + 8192 + boff);
                b2[2*np][0]=tt[0]; b2[2*np][1]=tt[1]; b2[2*np+1][0]=tt[2]; b2[2*np+1][1]=tt[3];
            }
#pragma unroll
            for(int ni=0;ni<4;ni++){
                mma16(s0[ni], qa0, b0[ni]);
                mma16(s1[ni], qa1, b1[ni]);
                mma16(s2[ni], qa2, b2[ni]);
            }
        }
        const int jb = jt*32;
        __half2 tl[4], th[4];
        if(allone){
#pragma unroll
            for(int ni=0;ni<4;ni++){
                unsigned ealo = h2ex2(packh2(fmaf(s0[ni][0],SCALE2,-m0lo),
                                             fmaf(s0[ni][1],SCALE2,-m0lo)));
                unsigned eahi = h2ex2(packh2(fmaf(s0[ni][2],SCALE2,-m0hi),
                                             fmaf(s0[ni][3],SCALE2,-m0hi)));
                unsigned eolo = h2ex2(packh2(fmaf(s1[ni][0],SCALE2,-m1lo),
                                             fmaf(s1[ni][1],SCALE2,-m1lo)));
                unsigned eohi = h2ex2(packh2(fmaf(s1[ni][2],SCALE2,-m1hi),
                                             fmaf(s1[ni][3],SCALE2,-m1hi)));
                __half2 s2lo = __floats2half2_rn(s2[ni][0]*SCALE2, s2[ni][1]*SCALE2);
                __half2 s2hi = __floats2half2_rn(s2[ni][2]*SCALE2, s2[ni][3]*SCALE2);
                tl[ni] = __hfma2(*(__half2*)&ealo, c0lo, __hfma2(*(__half2*)&eolo, c1lo, s2lo));
                th[ni] = __hfma2(*(__half2*)&eahi, c0hi, __hfma2(*(__half2*)&eohi, c1hi, s2hi));
            }
        } else {
#pragma unroll
            for(int ni=0;ni<4;ni++){
                float2 mk = *(const float2*)&maskadd[jb + 8*ni + 2*t];
                unsigned ealo = h2ex2(packh2(fmaf(s0[ni][0],SCALE2,mk.x)-m0lo,
                                             fmaf(s0[ni][1],SCALE2,mk.y)-m0lo));
                unsigned eahi = h2ex2(packh2(fmaf(s0[ni][2],SCALE2,mk.x)-m0hi,
                                             fmaf(s0[ni][3],SCALE2,mk.y)-m0hi));
                unsigned eolo = h2ex2(packh2(fmaf(s1[ni][0],SCALE2,mk.x)-m1lo,
                                             fmaf(s1[ni][1],SCALE2,mk.y)-m1lo));
                unsigned eohi = h2ex2(packh2(fmaf(s1[ni][2],SCALE2,mk.x)-m1hi,
                                             fmaf(s1[ni][3],SCALE2,mk.y)-m1hi));
                __half2 s2lo = __floats2half2_rn(fmaf(s2[ni][0],SCALE2,mk.x),
                                                 fmaf(s2[ni][1],SCALE2,mk.y));
                __half2 s2hi = __floats2half2_rn(fmaf(s2[ni][2],SCALE2,mk.x),
                                                 fmaf(s2[ni][3],SCALE2,mk.y));
                tl[ni] = __hfma2(*(__half2*)&ealo, c0lo, __hfma2(*(__half2*)&eolo, c1lo, s2lo));
                th[ni] = __hfma2(*(__half2*)&eahi, c0hi, __hfma2(*(__half2*)&eohi, c1hi, s2hi));
            }
        }
        __half2 hmlo = __hmax2(__hmax2(tl[0],tl[1]), __hmax2(tl[2],tl[3]));
        __half2 hmhi = __hmax2(__hmax2(th[0],th[1]), __hmax2(th[2],th[3]));
        float mx_lo = fmaxf(__low2float(hmlo), __high2float(hmlo));
        float mx_hi = fmaxf(__low2float(hmhi), __high2float(hmhi));
        mx_lo = fmaxf(mx_lo, __shfl_xor_sync(0xffffffffu, mx_lo, 1));
        mx_lo = fmaxf(mx_lo, __shfl_xor_sync(0xffffffffu, mx_lo, 2));
        mx_hi = fmaxf(mx_hi, __shfl_xor_sync(0xffffffffu, mx_hi, 1));
        mx_hi = fmaxf(mx_hi, __shfl_xor_sync(0xffffffffu, mx_hi, 2));
        const float mn_lo = fmaxf(m2_lo, mx_lo), mn_hi = fmaxf(m2_hi, mx_hi);
        const float f_lo = ex2(m2_lo - mn_lo), f_hi = ex2(m2_hi - mn_hi);
        m2_lo = mn_lo; m2_hi = mn_hi;

        const __half2 hm2lo = __float2half2_rn(m2_lo), hm2hi = __float2half2_rn(m2_hi);
        unsigned pf[2][4];
#pragma unroll
        for(int ni=0;ni<4;ni++){
            __half2 dlo = __hsub2(tl[ni], hm2lo);
            __half2 dhi = __hsub2(th[ni], hm2hi);
            pf[ni>>1][(ni&1)*2+0] = h2ex2(*(unsigned*)&dlo);
            pf[ni>>1][(ni&1)*2+1] = h2ex2(*(unsigned*)&dhi);
        }
        float ls[4] = {};
#pragma unroll
        for(int kg2=0;kg2<2;kg2++) mma16(ls, pf[kg2], ones2);
        l2_lo = l2_lo*f_lo + ls[0];
        l2_hi = l2_hi*f_hi + ls[2];
        if(__any_sync(0xffffffffu, (f_lo < 1.f) | (f_hi < 1.f))){
#pragma unroll
            for(int ni=0;ni<8;ni++){
                o[ni][0]*=f_lo; o[ni][1]*=f_lo; o[ni][2]*=f_hi; o[ni][3]*=f_hi;
            }
        }
        // PV with V2 (k=32 -> 2 k-groups)
#pragma unroll
        for(int kg2=0;kg2<2;kg2++){
            unsigned bf[8][2];
#pragma unroll
            for(int np=0;np<4;np++){
                const int row = rB0 + np*16;
                unsigned tt[4];
                ldsm4(tt, st + 12288 + (row<<7) + (((2*kg2+gB) ^ (row&7))<<4));
                bf[2*np][0]=tt[0]; bf[2*np][1]=tt[1];
                bf[2*np+1][0]=tt[2]; bf[2*np+1][1]=tt[3];
            }
#pragma unroll
            for(int ni=0;ni<8;ni++) mma16(o[ni], pf[kg2], bf[ni]);
        }
        __syncthreads();
        if(lt+2 < 32){
            unsigned* d = buf + (lt&1)*5120;
            const int j2 = 32*(jt+2);
            load_tile_async_h<32>(d,        k0g + (size_t)j2*HD, HD, 0, tid);
            load_tile_async_h<32>(d+1024,   k1g + (size_t)j2*HD, HD, 0, tid);
            load_tile_async_h<32>(d+2048,   k2g + (size_t)j2*HD, HD, 0, tid);
            load_tile32_async_h<64>(d+3072, v2g, SS, j2, tid);
        }
        CP_COMMIT();
    }

    // store partial (o unnormalized, m, l)
    const size_t base = ((size_t)zh*24 + bh)*SS;
#pragma unroll
    for(int ni=0;ni<8;ni++){
        const int d = 8*ni + 2*t;
        float2 plo; plo.x = o[ni][0]; plo.y = o[ni][1];
        float2 phi; phi.x = o[ni][2]; phi.y = o[ni][3];
        *(float2*)(g_po + (base + r_lo)*HD + d) = plo;
        *(float2*)(g_po + (base + r_hi)*HD + d) = phi;
    }
    if(t==0){
        g_pm[base + r_lo] = m2_lo; g_pl[base + r_lo] = l2_lo;
        g_pm[base + r_hi] = m2_hi; g_pl[base + r_hi] = l2_hi;
    }
}

// ---------------------------------------------------------------------------
// K4: merge_b — combine the two j-half partials into ctx (n=2).
// ---------------------------------------------------------------------------
__global__ void __launch_bounds__(256) merge_b()
{
    const int idx = blockIdx.x*256 + threadIdx.x;
    const int grp = idx & 7;
    const int rowg = idx >> 3;
    const int bh = rowg >> 11, r = rowg & 2047;
    const int b = bh/NHEAD, h = bh%NHEAD;

    const float m0 = g_pm[rowg], m1 = g_pm[24*SS + rowg];
    const float l0 = g_pl[rowg], l1 = g_pl[24*SS + rowg];
    const float m = fmaxf(m0, m1);
    const float f0 = ex2(m0 - m), f1 = ex2(m1 - m);
    const float il = 1.f/(l0*f0 + l1*f1);
    const float c0 = f0*il, c1 = f1*il;

    const size_t o0 = (size_t)rowg*HD + grp*8;
    const size_t o1 = (size_t)(24*SS + rowg)*HD + grp*8;
    float4 a0 = *(const float4*)(g_po + o0);
    float4 a1 = *(const float4*)(g_po + o0 + 4);
    float4 b0 = *(const float4*)(g_po + o1);
    float4 b1 = *(const float4*)(g_po + o1 + 4);

    __align__(16) __half2 hh[4];
    hh[0] = __floats2half2_rn(a0.x*c0 + b0.x*c1, a0.y*c0 + b0.y*c1);
    hh[1] = __floats2half2_rn(a0.z*c0 + b0.z*c1, a0.w*c0 + b0.w*c1);
    hh[2] = __floats2half2_rn(a1.x*c0 + b1.x*c1, a1.y*c0 + b1.y*c1);
    hh[3] = __floats2half2_rn(a1.z*c0 + b1.z*c1, a1.w*c0 + b1.w*c1);
    *(uint4*)(g_ctx + (((size_t)2*BB + b)*SS + r)*HH + h*HD + grp*8) = *(uint4*)hh;
}

// ---------------------------------------------------------------------------
// K5: output projection.  Block 128x128. grid (6, 32, 3). fp32 out + bias.
// ---------------------------------------------------------------------------
__global__ void __launch_bounds__(256,2) outproj_tc(
    const float* __restrict__ bo, float* __restrict__ out)
{
    extern __shared__ unsigned smu[];
    unsigned* sA = smu;
    unsigned* sB = smu + 2*128*32;
    const int n = blockIdx.z;
    const __half* X   = g_ctx + (size_t)n*MM*HH;
    const __half* Wt  = g_wt + (size_t)(9+n)*HH*HH;
    const float* bias = bo + (size_t)n*HH;
    float* O = out + (size_t)n*MM*HH;

    const int m0 = blockIdx.y*128, e0 = blockIdx.x*128;
    const int tid = threadIdx.x, wid = tid>>5, lane = tid&31;
    const int gid = lane>>2, tig = lane&3;
    const int wm = wid & 1, wn = wid >> 1;

    float acc[4][4][4] = {};
    gemm_body_h<HH,128,128>(sA, sB, X + (size_t)m0*HH, HH, Wt + (size_t)e0*HH, HH,
                            tid, wm*64, wn*32, gid, tig, acc);

#pragma unroll
    for(int mi=0;mi<4;mi++)
#pragma unroll
    for(int ni=0;ni<4;ni++){
        const int e = e0 + wn*32 + ni*8 + 2*tig;
        const float2 b2 = *(const float2*)(bias + e);
#pragma unroll
        for(int h2=0;h2<2;h2++){
            int m = m0 + wm*64 + mi*16 + gid + h2*8;
            float2 oo; oo.x = acc[mi][ni][h2*2+0] + b2.x; oo.y = acc[mi][ni][h2*2+1] + b2.y;
            *(float2*)(O + (size_t)m*HH + e) = oo;
        }
    }
}

// ---------------------------------------------------------------------------
// Launch
// ---------------------------------------------------------------------------
extern "C" void kernel_launch(void* const* d_in, const int* in_sizes, int n_in,
                              void* d_out, int out_size)
{
    (void)in_sizes; (void)n_in; (void)out_size;
    const float* hidden = (const float*)d_in[0];
    // d_in[1] aspect_weights, d_in[2] opinion_weights: per-query-row biases cancel in softmax
    const int*   mask   = (const int*)  d_in[3];
    const float* Wq = (const float*)d_in[4];  const float* bq = (const float*)d_in[5];
    const float* Wk = (const float*)d_in[6];  const float* bk = (const float*)d_in[7];
    const float* Wv = (const float*)d_in[8];  const float* bv = (const float*)d_in[9];
    const float* Wo = (const float*)d_in[10]; const float* bo = (const float*)d_in[11];
    float* out = (float*)d_out;

    const int smemAB = (2*128*32 + 2*128*32) * 4;              // 64 KB (proj/outproj)
    const int smemFA = (2048 + 4096 + 3*2048 + 3*2048) * 4;    // 72 KB (flash_a)
    const int smemFB = (2048 + 3*4096 + 2*5120) * 4;           // 96 KB (flash_b)
    cudaFuncSetAttribute(proj_tc,    cudaFuncAttributeMaxDynamicSharedMemorySize, smemAB);
    cudaFuncSetAttribute(flash_a,    cudaFuncAttributeMaxDynamicSharedMemorySize, smemFA);
    cudaFuncSetAttribute(flash_b,    cudaFuncAttributeMaxDynamicSharedMemorySize, smemFB);
    cudaFuncSetAttribute(outproj_tc, cudaFuncAttributeMaxDynamicSharedMemorySize, smemAB);

    conv_hidden<<<dim3(MM*HH/2048), 256>>>(hidden);
    transpose_w<<<dim3(24,24,12), 256>>>(Wq, Wk, Wv, Wo);
    proj_tc    <<<dim3(6, 32, 9), 256, smemAB>>>(bq, bk, bv);
    flash_a    <<<dim3(16, 24, 2), 256, smemFA>>>(mask);
    flash_b    <<<dim3(16, 24, 2), 256, smemFB>>>(mask);
    merge_b    <<<dim3(1536), 256>>>();
    outproj_tc <<<dim3(6, 32, 3), 256, smemAB>>>(bo, out);
}